// round 3
// baseline (speedup 1.0000x reference)
#include <cuda_runtime.h>
#include <cstddef>

#define SQ   1024     // sequence length
#define BB   32       // batch
#define EE   256      // input dim
#define HH   256      // hidden
#define G4   1024     // 4*H
#define KSH  2        // SHARE
#define NCTA_DIR 64
#define NTHREADS 256
#define STRIDE 516    // padded SMEM row stride (floats)

// ---------------- device scratch (static: no allocs allowed) ----------------
__device__ float g_h[2][2][BB*HH];           // [dir][parity][b*H + j]
__device__ float g_c[2][2][BB*HH];
__device__ float g_s[2][2][KSH*BB*HH];       // [dir][parity][(k*B+b)*H + j]
__device__ unsigned int g_barcnt[2];
__device__ float g_XZ[(size_t)2*SQ*BB*G4];         // [d][t][b][4H]  (bias folded)
__device__ float g_XR[(size_t)2*SQ*KSH*BB*HH];     // [d][t][k][b][H] (br folded)

// ---------------- init: zero states + barrier counters ----------------
__global__ void init_k() {
    int i = blockIdx.x * blockDim.x + threadIdx.x;
    if (i < 2*2*BB*HH) { ((float*)g_h)[i] = 0.f; ((float*)g_c)[i] = 0.f; }
    if (i < 2*2*KSH*BB*HH) ((float*)g_s)[i] = 0.f;
    if (i < 2) g_barcnt[i] = 0u;
}

// ---------------- precompute GEMM: XZ = x@Wx + b ; XR = x@Wrx + br ----------------
// A: (M=32768, K=256) rows m=(t*32+b); Bmat: (256, 1536) = [Wx | Wrx_flat]
__global__ void __launch_bounds__(256) pre_gemm(
    const float* __restrict__ x,
    const float* __restrict__ Wx_f, const float* __restrict__ Wrx_f,
    const float* __restrict__ b_f,  const float* __restrict__ br_f,
    const float* __restrict__ Wx_r, const float* __restrict__ Wrx_r,
    const float* __restrict__ b_r,  const float* __restrict__ br_r)
{
    __shared__ float As[16*68];   // As[k][m], padded
    __shared__ float Bs[16*68];   // Bs[k][n], padded

    const int tid = threadIdx.x;
    const int d  = blockIdx.z;
    const int n0 = blockIdx.x * 64;
    const int m0 = blockIdx.y * 64;

    const float* Wx  = d ? Wx_r  : Wx_f;
    const float* Wrx = d ? Wrx_r : Wrx_f;
    const float* bz  = d ? b_r   : b_f;
    const float* brz = d ? br_r  : br_f;

    const int tm = tid & 15, tn = tid >> 4;       // 16x16 thread grid, 4x4 microtile
    const int ar = tid >> 2, akq = (tid & 3) << 2;
    const int bkk = tid >> 4, bn4 = (tid & 15) << 2;

    float acc[4][4] = {};

    for (int k0 = 0; k0 < 256; k0 += 16) {
        // load A tile 64x16 to regs
        int m = m0 + ar;
        int bb = m & 31, t = m >> 5;
        float4 av = *(const float4*)&x[((size_t)bb*SQ + t)*EE + k0 + akq];
        // load B tile 16x64 to regs
        int n = n0 + bn4;
        float4 bv;
        if (n < 1024) {
            bv = *(const float4*)&Wx[(size_t)(k0 + bkk)*G4 + n];
        } else {
            int rc = n - 1024, ks = rc >> 8, j = rc & 255;
            bv = *(const float4*)&Wrx[((size_t)ks*256 + (k0 + bkk))*256 + j];
        }
        __syncthreads();
        As[(akq+0)*68 + ar] = av.x;
        As[(akq+1)*68 + ar] = av.y;
        As[(akq+2)*68 + ar] = av.z;
        As[(akq+3)*68 + ar] = av.w;
        *(float4*)&Bs[bkk*68 + bn4] = bv;
        __syncthreads();
        #pragma unroll
        for (int kk = 0; kk < 16; ++kk) {
            float4 a  = *(const float4*)&As[kk*68 + tm*4];
            float4 b4 = *(const float4*)&Bs[kk*68 + tn*4];
            acc[0][0] += a.x*b4.x; acc[0][1] += a.x*b4.y; acc[0][2] += a.x*b4.z; acc[0][3] += a.x*b4.w;
            acc[1][0] += a.y*b4.x; acc[1][1] += a.y*b4.y; acc[1][2] += a.y*b4.z; acc[1][3] += a.y*b4.w;
            acc[2][0] += a.z*b4.x; acc[2][1] += a.z*b4.y; acc[2][2] += a.z*b4.z; acc[2][3] += a.z*b4.w;
            acc[3][0] += a.w*b4.x; acc[3][1] += a.w*b4.y; acc[3][2] += a.w*b4.z; acc[3][3] += a.w*b4.w;
        }
    }
    // epilogue: add bias, scatter to XZ / XR
    #pragma unroll
    for (int i = 0; i < 4; ++i) {
        int m = m0 + tm*4 + i;
        int t = m >> 5, bb = m & 31;
        #pragma unroll
        for (int j = 0; j < 4; ++j) {
            int n = n0 + tn*4 + j;
            float v = acc[i][j];
            if (n < 1024) {
                v += bz[n];
                g_XZ[((size_t)d*32768 + m)*1024 + n] = v;
            } else {
                int rc = n - 1024, ks = rc >> 8, jj = rc & 255;
                v += brz[ks*256 + jj];
                g_XR[((((size_t)d*SQ + t)*KSH + ks)*BB + bb)*256 + jj] = v;
            }
        }
    }
}

// ---------------- barrier across the 64 CTAs of one direction ----------------
__device__ __forceinline__ void dir_barrier(volatile unsigned int* bc, unsigned int target) {
    __syncthreads();
    if (threadIdx.x == 0) {
        __threadfence();                       // drain my writes to L2
        atomicAdd((unsigned int*)bc, 1u);      // RED (no return use)
        int spins = 0;
        while (*bc < target) {
            if (((++spins) & 15) == 0) __nanosleep(64);
        }
        __threadfence();                       // CCTL.IVALL: invalidate L1D before consuming
    }
    __syncthreads();
}

#define DOT4(acc, hv, wv) acc += (hv).x*(wv).x + (hv).y*(wv).y + (hv).z*(wv).z + (hv).w*(wv).w

// ---------------- persistent recurrent kernel ----------------
// grid: 128 CTAs; CTA -> (dir = blk>>6, rank = blk&63). 256 threads.
__global__ void __launch_bounds__(NTHREADS, 1) rnn_persist(
    const float* __restrict__ mask,
    const float* __restrict__ Wh_f, const float* __restrict__ Ws_f, const float* __restrict__ Wrh_f,
    const float* __restrict__ Wh_r, const float* __restrict__ Ws_r, const float* __restrict__ Wrh_r,
    const int*   __restrict__ idx_p,
    float* __restrict__ out)
{
    extern __shared__ float sm[];
    float* hsS = sm;                                 // [32][516]  h|s_idx (phase1), h_new (phase2)
    float* Wt1 = sm + 32*STRIDE;                     // [16][516]  col-major [Wh;Ws] slice
    float* WrS = Wt1 + 16*STRIDE;                    // [8][516]   col-major Wrh slice
    float* zp  = WrS + 8*STRIDE;                     // [4][16][33] k-split partials
    float* zXZ = zp + 4*16*33;                       // [16][33]
    float* zXR = zXZ + 16*33;                        // [8][33]

    const int tid  = threadIdx.x;
    const int d    = blockIdx.x >> 6;
    const int rank = blockIdx.x & 63;

    const float* Wh  = d ? Wh_r  : Wh_f;
    const float* Ws  = d ? Ws_r  : Ws_f;
    const float* Wrh = d ? Wrh_r : Wrh_f;
    const int sidx = *idx_p;

    // ---- load weight slices once (SMEM-resident for all 1024 steps) ----
    // CTA owns z-cols zcol(g,q) = g*256 + rank*4 + q  (lc = g*4+q)
    for (int i = tid; i < 16*512; i += NTHREADS) {
        int lc = i >> 9, k = i & 511;
        int zcol = ((lc >> 2) << 8) + rank*4 + (lc & 3);
        Wt1[lc*STRIDE + k] = (k < 256) ? Wh[(size_t)k*G4 + zcol] : Ws[(size_t)(k-256)*G4 + zcol];
    }
    // CTA owns r-cols rc = rank*8 + j2  (ks = rc>>8, j = rc&255)
    for (int i = tid; i < 8*256; i += NTHREADS) {
        int j2 = i >> 8, k = i & 255;
        int rc = rank*8 + j2;
        int ks = rc >> 8, j = rc & 255;
        WrS[j2*STRIDE + k] = Wrh[((size_t)ks*256 + k)*256 + j];
    }

    unsigned int nbar = 0;
    volatile unsigned int* bc = &g_barcnt[d];

    const int c2 = tid & 7;          // col pair: lc0 = c2*2
    const int bg = (tid >> 3) & 7;   // batch quad: b0 = bg*4
    const int kh = tid >> 6;         // k quarter: [kh*128, kh*128+128)

    for (int u = 0; u < SQ; ++u) {
        const int p = u & 1, p1 = p ^ 1;
        const int tx = d ? (SQ-1-u) : u;     // x/mask/output time index

        // ---- phase1a: stage [h | s_idx] into SMEM, prefetch XZ slice ----
        {
            const float* hsrc = g_h[d][p];
            const float* ssrc = g_s[d][p] + sidx*BB*HH;
            for (int i = tid; i < BB*512; i += NTHREADS) {
                int b = i >> 9, k = i & 511;
                hsS[b*STRIDE + k] = (k < 256) ? hsrc[b*256 + k] : ssrc[b*256 + (k - 256)];
            }
            if (tid < 128) {
                int b = tid >> 2, g = tid & 3;
                float4 v = *(const float4*)&g_XZ[(((size_t)d*SQ + tx)*BB + b)*G4 + g*256 + rank*4];
                zXZ[(g*4+0)*33 + b] = v.x;
                zXZ[(g*4+1)*33 + b] = v.y;
                zXZ[(g*4+2)*33 + b] = v.z;
                zXZ[(g*4+3)*33 + b] = v.w;
            }
        }
        __syncthreads();

        // ---- phase1b: z-GEMM  [h|s](32x512) @ W1(512x16cols), k split 4 ways ----
        {
            float a00=0,a01=0,a10=0,a11=0,a20=0,a21=0,a30=0,a31=0;
            const float* wp0 = Wt1 + (c2*2)*STRIDE + kh*128;
            const float* wp1 = wp0 + STRIDE;
            const float* hp  = hsS + (bg*4)*STRIDE + kh*128;
            #pragma unroll 8
            for (int kk = 0; kk < 128; kk += 4) {
                float4 w0 = *(const float4*)(wp0 + kk);
                float4 w1 = *(const float4*)(wp1 + kk);
                float4 h0 = *(const float4*)(hp + kk);
                float4 h1 = *(const float4*)(hp + STRIDE + kk);
                float4 h2 = *(const float4*)(hp + 2*STRIDE + kk);
                float4 h3 = *(const float4*)(hp + 3*STRIDE + kk);
                DOT4(a00, h0, w0); DOT4(a01, h0, w1);
                DOT4(a10, h1, w0); DOT4(a11, h1, w1);
                DOT4(a20, h2, w0); DOT4(a21, h2, w1);
                DOT4(a30, h3, w0); DOT4(a31, h3, w1);
            }
            int lc0 = c2*2, lc1 = lc0 + 1, b0 = bg*4;
            zp[(kh*16 + lc0)*33 + b0+0] = a00;  zp[(kh*16 + lc1)*33 + b0+0] = a01;
            zp[(kh*16 + lc0)*33 + b0+1] = a10;  zp[(kh*16 + lc1)*33 + b0+1] = a11;
            zp[(kh*16 + lc0)*33 + b0+2] = a20;  zp[(kh*16 + lc1)*33 + b0+2] = a21;
            zp[(kh*16 + lc0)*33 + b0+3] = a30;  zp[(kh*16 + lc1)*33 + b0+3] = a31;
        }
        __syncthreads();

        // ---- phase1c: reduce k-partials, gates, h/c update, write outputs ----
        if (tid < 128) {
            int q = tid & 3, b = tid >> 2;
            int hcol = rank*4 + q;
            float zg[4];
            #pragma unroll
            for (int g = 0; g < 4; ++g) {
                int lc = g*4 + q;
                zg[g] = zp[(0*16+lc)*33 + b] + zp[(1*16+lc)*33 + b]
                      + zp[(2*16+lc)*33 + b] + zp[(3*16+lc)*33 + b]
                      + zXZ[lc*33 + b];
            }
            float ig = 1.f/(1.f + __expf(-zg[0]));
            float fg = 1.f/(1.f + __expf(-zg[1]));
            float gg = tanhf(zg[2]);
            float og = 1.f/(1.f + __expf(-zg[3]));
            float c_old = g_c[d][p][b*256 + hcol];
            float h_old = hsS[b*STRIDE + hcol];
            float c_new = fg*c_old + ig*gg;
            float h_new = og*tanhf(c_new);
            float mv = mask[b*SQ + tx];
            float hv = mv*h_new + (1.f - mv)*h_old;
            float cv = mv*c_new + (1.f - mv)*c_old;
            g_h[d][p1][b*256 + hcol] = hv;
            g_c[d][p1][b*256 + hcol] = cv;
            out[((size_t)tx*BB + b)*512 + d*256 + hcol] = hv;
            out[(size_t)SQ*BB*512 + ((size_t)tx*BB + b)*512 + d*256 + hcol] = cv;
        }
        dir_barrier(bc, (++nbar) * NCTA_DIR);

        // ---- phase2a: stage new h, prefetch XR slice ----
        {
            const float* hnp = g_h[d][p1];
            for (int i = tid; i < BB*256; i += NTHREADS) {
                int b = i >> 8, k = i & 255;
                hsS[b*STRIDE + k] = hnp[b*256 + k];
            }
            if (tid < 64) {
                int b = tid >> 1, half = tid & 1;
                int rc0 = rank*8;
                int ks = rc0 >> 8, j0 = (rc0 & 255) + half*4;
                float4 v = *(const float4*)&g_XR[((((size_t)d*SQ + tx)*KSH + ks)*BB + b)*256 + j0];
                zXR[(half*4+0)*33 + b] = v.x;
                zXR[(half*4+1)*33 + b] = v.y;
                zXR[(half*4+2)*33 + b] = v.z;
                zXR[(half*4+3)*33 + b] = v.w;
            }
        }
        __syncthreads();

        // ---- phase2b: r-GEMM + s update ----
        {
            int j2 = tid & 7, b = tid >> 3;   // 8 cols x 32 batch = 256 outputs
            const float* wp = WrS + j2*STRIDE;
            const float* hp = hsS + b*STRIDE;
            float acc = 0.f;
            #pragma unroll 8
            for (int k = 0; k < 256; k += 4) {
                float4 w = *(const float4*)(wp + k);
                float4 h = *(const float4*)(hp + k);
                DOT4(acc, h, w);
            }
            int rc = rank*8 + j2;
            int ks = rc >> 8, j = rc & 255;
            float rg = 1.f/(1.f + __expf(-(acc + zXR[j2*33 + b])));
            float s_old = g_s[d][p][(ks*BB + b)*256 + j];
            float c_cur = g_c[d][p1][b*256 + j];
            float mv = mask[b*SQ + tx];
            float s_new = rg*s_old + (1.f - rg)*c_cur;
            float sv = mv*s_new + (1.f - mv)*s_old;
            g_s[d][p1][(ks*BB + b)*256 + j] = sv;
            out[(size_t)2*SQ*BB*512 + (((size_t)ks*SQ + tx)*BB + b)*512 + d*256 + j] = sv;
        }
        dir_barrier(bc, (++nbar) * NCTA_DIR);
    }
}

// SMEM: 32*516 + 16*516 + 8*516 + 4*16*33 + 16*33 + 8*33 = 31800 floats
#define SMEM_BYTES (31800 * 4)

extern "C" void kernel_launch(void* const* d_in, const int* in_sizes, int n_in,
                              void* d_out, int out_size) {
    const float* x     = (const float*)d_in[0];
    const float* mask  = (const float*)d_in[1];
    const float* Wx    = (const float*)d_in[2];
    const float* Wh    = (const float*)d_in[3];
    const float* Ws    = (const float*)d_in[4];
    const float* bz    = (const float*)d_in[5];
    const float* Wrx   = (const float*)d_in[6];
    const float* Wrh   = (const float*)d_in[7];
    const float* br    = (const float*)d_in[8];
    const float* Wx_r  = (const float*)d_in[9];
    const float* Wh_r  = (const float*)d_in[10];
    const float* Ws_r  = (const float*)d_in[11];
    const float* b_r   = (const float*)d_in[12];
    const float* Wrx_r = (const float*)d_in[13];
    const float* Wrh_r = (const float*)d_in[14];
    const float* br_r  = (const float*)d_in[15];
    const int*   idxp  = (const int*)d_in[16];
    float* out = (float*)d_out;

    (void)cudaFuncSetAttribute(rnn_persist,
                               cudaFuncAttributeMaxDynamicSharedMemorySize, SMEM_BYTES);

    init_k<<<256, 256>>>();
    pre_gemm<<<dim3(24, 512, 2), 256>>>(x, Wx, Wrx, bz, br, Wx_r, Wrx_r, b_r, br_r);
    rnn_persist<<<128, NTHREADS, SMEM_BYTES>>>(mask, Wh, Ws, Wrh,
                                               Wh_r, Ws_r, Wrh_r, idxp, out);
}

// round 4
// speedup vs baseline: 1.8078x; 1.8078x over previous
#include <cuda_runtime.h>
#include <cstddef>

#define SQ   1024
#define BB   32
#define EE   256
#define HH   256
#define G4   1024
#define KSH  2
#define NCTA_DIR 64
#define NTHREADS 256

// SMEM strides (floats). Rows hold k with +16-float skew per 32-k block,
// row stride == 4 (mod 32 banks) so thread-varying row index shifts bank group.
#define HST 772   // hsS: 512 k + 16 blocks*16 skew = 768, +4
#define WST 772   // Wt1: same k-extent as hsS
#define W2ST 388  // WrS: 256 k + 8*16 = 384, +4

// ---------------- device scratch ----------------
__device__ float g_h[2][2][BB*HH];
__device__ float g_c[2][2][BB*HH];
__device__ float g_s[2][2][KSH*BB*HH];
__device__ unsigned int g_barcnt[2];
__device__ float g_XZ[(size_t)2*SQ*BB*G4];
__device__ float g_XR[(size_t)2*SQ*KSH*BB*HH];

__global__ void init_k() {
    int i = blockIdx.x * blockDim.x + threadIdx.x;
    if (i < 2*2*BB*HH) { ((float*)g_h)[i] = 0.f; ((float*)g_c)[i] = 0.f; }
    if (i < 2*2*KSH*BB*HH) ((float*)g_s)[i] = 0.f;
    if (i < 2) g_barcnt[i] = 0u;
}

// ---------------- f32x2 packed FMA (Blackwell FFMA2, PTX-only) ----------------
__device__ __forceinline__ void fma2(unsigned long long &d,
                                     unsigned long long a, unsigned long long b) {
    asm("fma.rn.f32x2 %0, %1, %2, %0;" : "+l"(d) : "l"(a), "l"(b));
}
__device__ __forceinline__ float ull_sum(unsigned long long v) {
    return __uint_as_float((unsigned)v) + __uint_as_float((unsigned)(v >> 32));
}
__device__ __forceinline__ void red_release(unsigned int* p) {
    asm volatile("red.release.gpu.global.add.u32 [%0], 1;" :: "l"(p) : "memory");
}
__device__ __forceinline__ unsigned int ld_acquire(const unsigned int* p) {
    unsigned int v;
    asm volatile("ld.acquire.gpu.global.u32 %0, [%1];" : "=r"(v) : "l"(p) : "memory");
    return v;
}
__device__ __forceinline__ float4 ldcg4(const float* p) {
    return __ldcg((const float4*)p);
}

// ---------------- precompute GEMM (f32x2, 128x64 tile, 8x8 micro) ----------------
// C(32768 x 1536) = A(32768 x 256) @ Bmat(256 x 1536) = [Wx | Wrx_flat], bias folded.
__global__ void __launch_bounds__(128) pre_gemm(
    const float* __restrict__ x,
    const float* __restrict__ Wx_f, const float* __restrict__ Wrx_f,
    const float* __restrict__ b_f,  const float* __restrict__ br_f,
    const float* __restrict__ Wx_r, const float* __restrict__ Wrx_r,
    const float* __restrict__ b_r,  const float* __restrict__ br_r)
{
    __shared__ float As[128*36];   // [m][k] k-contig, stride 36
    __shared__ float Bs[64*36];    // [n][k] k-contig, stride 36

    const int tid = threadIdx.x;
    const int d  = blockIdx.z;
    const int n0 = blockIdx.x * 64;
    const int m0 = blockIdx.y * 128;

    const float* Wx  = d ? Wx_r  : Wx_f;
    const float* Wrx = d ? Wrx_r : Wrx_f;
    const float* bz  = d ? b_r   : b_f;
    const float* brz = d ? br_r  : br_f;

    const int mg = tid & 15, ng = tid >> 4;    // rows m=mg+16i, cols n=ng+8j

    unsigned long long acc[8][8];
    #pragma unroll
    for (int i = 0; i < 8; ++i)
        #pragma unroll
        for (int j = 0; j < 8; ++j) acc[i][j] = 0ull;

    for (int k0 = 0; k0 < 256; k0 += 32) {
        __syncthreads();
        // A tile: 128 rows x 32 k  (1024 float4s, 8 per thread)
        #pragma unroll
        for (int r = 0; r < 8; ++r) {
            int v = tid + r * 128;
            int row = v >> 3, k4 = (v & 7) << 2;
            int m = m0 + row;
            float4 av = *(const float4*)&x[((size_t)(m & 31)*SQ + (m >> 5))*EE + k0 + k4];
            *(float4*)&As[row*36 + k4] = av;
        }
        // B tile: 64 n x 32 k, transposed from k-major global (512 float4s, 4/thr)
        #pragma unroll
        for (int r = 0; r < 4; ++r) {
            int v = tid + r * 128;
            int kk = v >> 4, n4 = (v & 15) << 2;
            int n = n0 + n4;
            float4 bv;
            if (n < 1024) {
                bv = *(const float4*)&Wx[(size_t)(k0 + kk)*G4 + n];
            } else {
                int rc = n - 1024, ks = rc >> 8, j = rc & 255;
                bv = *(const float4*)&Wrx[((size_t)ks*256 + (k0 + kk))*256 + j];
            }
            Bs[(n4+0)*36 + kk] = bv.x;
            Bs[(n4+1)*36 + kk] = bv.y;
            Bs[(n4+2)*36 + kk] = bv.z;
            Bs[(n4+3)*36 + kk] = bv.w;
        }
        __syncthreads();
        #pragma unroll
        for (int kk = 0; kk < 32; kk += 4) {
            ulonglong2 a[8];
            #pragma unroll
            for (int i = 0; i < 8; ++i)
                a[i] = *(const ulonglong2*)&As[(mg + 16*i)*36 + kk];
            #pragma unroll
            for (int j = 0; j < 8; ++j) {
                ulonglong2 bb = *(const ulonglong2*)&Bs[(ng + 8*j)*36 + kk];
                #pragma unroll
                for (int i = 0; i < 8; ++i) {
                    fma2(acc[i][j], a[i].x, bb.x);
                    fma2(acc[i][j], a[i].y, bb.y);
                }
            }
        }
    }
    // epilogue
    #pragma unroll
    for (int i = 0; i < 8; ++i) {
        int m = m0 + mg + 16*i;
        int t = m >> 5, bbx = m & 31;
        #pragma unroll
        for (int j = 0; j < 8; ++j) {
            int n = n0 + ng + 8*j;
            float v = ull_sum(acc[i][j]);
            if (n < 1024) {
                v += bz[n];
                g_XZ[((size_t)d*32768 + m)*1024 + n] = v;
            } else {
                int rc = n - 1024, ks = rc >> 8, jj = rc & 255;
                v += brz[ks*256 + jj];
                g_XR[((((size_t)d*SQ + t)*KSH + ks)*BB + bbx)*256 + jj] = v;
            }
        }
    }
}

// ---------------- barrier across the 64 CTAs of one direction ----------------
__device__ __forceinline__ void dir_barrier(unsigned int* bc, unsigned int target) {
    __syncthreads();
    if (threadIdx.x == 0) {
        red_release(bc);                 // release: publish prior STGs to L2
        int n = 0;
        while (ld_acquire(bc) < target) {
            if (((++n) & 15) == 0) __nanosleep(64);
        }
    }
    __syncthreads();
}

// ---------------- persistent recurrent kernel ----------------
__global__ void __launch_bounds__(NTHREADS, 1) rnn_persist(
    const float* __restrict__ mask,
    const float* __restrict__ Wh_f, const float* __restrict__ Ws_f, const float* __restrict__ Wrh_f,
    const float* __restrict__ Wh_r, const float* __restrict__ Ws_r, const float* __restrict__ Wrh_r,
    const int*   __restrict__ idx_p,
    float* __restrict__ out)
{
    extern __shared__ float sm[];
    float* hsS   = sm;                 // [32][772]  staged h|s (k-skewed)
    float* Wt1   = hsS + 32*HST;       // [16][772]  [Wh;Ws] slice, col-major k-skewed
    float* WrS   = Wt1 + 16*WST;       // [8][388]   Wrh slice
    float* zp    = WrS + 8*W2ST;       // [8][16][33] k-partials (phase2 reuses [8][8][33])
    float* zXZ   = zp + 8*16*33;       // [16][33]
    float* zXR   = zXZ + 16*33;        // [8][33]
    float* maskS = zXR + 8*33;         // [32]

    const int tid  = threadIdx.x;
    const int d    = blockIdx.x >> 6;
    const int rank = blockIdx.x & 63;

    const float* Wh  = d ? Wh_r  : Wh_f;
    const float* Ws  = d ? Ws_r  : Ws_f;
    const float* Wrh = d ? Wrh_r : Wrh_f;
    const int sidx = *idx_p;

    // ---- load weight slices once, k-skewed ----
    // z-cols: lc in [0,16): zcol = (lc>>2)*256 + rank*4 + (lc&3)  (lc = g*4+q)
    for (int i = tid; i < 16*512; i += NTHREADS) {
        int lc = i >> 9, k = i & 511;
        int zcol = ((lc >> 2) << 8) + rank*4 + (lc & 3);
        float w = (k < 256) ? Wh[(size_t)k*G4 + zcol] : Ws[(size_t)(k-256)*G4 + zcol];
        Wt1[lc*WST + k + ((k >> 5) << 4)] = w;
    }
    // r-cols: this CTA owns rc = rank*8 + col, all same ks = rank>>5
    {
        const int ksg = rank >> 5, j0 = (rank & 31) * 8;
        for (int i = tid; i < 8*256; i += NTHREADS) {
            int col = i >> 8, k = i & 255;
            WrS[col*W2ST + k + ((k >> 5) << 4)] = Wrh[((size_t)ksg*256 + k)*256 + j0 + col];
        }
    }

    unsigned int nbar = 0;
    unsigned int* bc = &g_barcnt[d];

    // thread decomposition: tid = ks*16 + bg*4 + cg
    const int cg = tid & 3;
    const int bg = (tid >> 2) & 3;
    const int ks = tid >> 4;           // 0..15

    for (int u = 0; u < SQ; ++u) {
        const int p = u & 1, p1 = p ^ 1;
        const int tx = d ? (SQ-1-u) : u;

        // ---- phase1a: stage [h|s_idx] (L2 via .cg) + prefetch XZ + mask ----
        {
            const float* hsrc = g_h[d][p];
            const float* ssrc = g_s[d][p] + sidx*BB*HH;
            #pragma unroll
            for (int r = 0; r < 16; ++r) {
                int v = tid + r * NTHREADS;            // float4 id, 4096 total
                int b = v >> 7, kq = (v & 127) << 2;
                float4 vv = (kq < 256) ? ldcg4(&hsrc[b*256 + kq])
                                       : ldcg4(&ssrc[b*256 + kq - 256]);
                *(float4*)&hsS[b*HST + kq + ((kq >> 5) << 4)] = vv;
            }
            if (tid < 128) {
                int b = tid >> 2, g = tid & 3;
                float4 v = ldcg4(&g_XZ[(((size_t)d*SQ + tx)*BB + b)*G4 + (g << 8) + rank*4]);
                zXZ[(g*4+0)*33 + b] = v.x;
                zXZ[(g*4+1)*33 + b] = v.y;
                zXZ[(g*4+2)*33 + b] = v.z;
                zXZ[(g*4+3)*33 + b] = v.w;
            }
            if (tid < 32) maskS[tid] = __ldg(&mask[tid*SQ + tx]);
        }
        __syncthreads();

        // ---- phase1b: z-GEMM 32x512 @ 512x16, f32x2, 8x4 micro, ksplit 16 ----
        {
            const float* hp = hsS + bg*HST + ks*48;
            const float* wp = Wt1 + cg*WST + ks*48;
            unsigned long long acc[8][4];
            #pragma unroll
            for (int i = 0; i < 8; ++i)
                #pragma unroll
                for (int j = 0; j < 4; ++j) acc[i][j] = 0ull;
            #pragma unroll
            for (int kk = 0; kk < 32; kk += 4) {
                ulonglong2 hr[8];
                #pragma unroll
                for (int i = 0; i < 8; ++i)
                    hr[i] = *(const ulonglong2*)(hp + i*4*HST + kk);
                #pragma unroll
                for (int j = 0; j < 4; ++j) {
                    ulonglong2 wv = *(const ulonglong2*)(wp + j*4*WST + kk);
                    #pragma unroll
                    for (int i = 0; i < 8; ++i) {
                        fma2(acc[i][j], hr[i].x, wv.x);
                        fma2(acc[i][j], hr[i].y, wv.y);
                    }
                }
            }
            const int store = !(ks & 1);
            const int kp = ks >> 1;
            #pragma unroll
            for (int i = 0; i < 8; ++i)
                #pragma unroll
                for (int j = 0; j < 4; ++j) {
                    float s = ull_sum(acc[i][j]);
                    s += __shfl_xor_sync(0xffffffffu, s, 16);
                    if (store) zp[(kp*16 + cg + 4*j)*33 + bg + 4*i] = s;
                }
        }
        __syncthreads();

        // ---- phase1c: reduce partials, gates, h/c update + output ----
        if (tid < 128) {
            int q = tid & 3, b = tid >> 2;
            int hcol = rank*4 + q;
            float zg[4];
            #pragma unroll
            for (int g = 0; g < 4; ++g) {
                int lc = g*4 + q;
                float s = zXZ[lc*33 + b];
                #pragma unroll
                for (int kp = 0; kp < 8; ++kp) s += zp[(kp*16 + lc)*33 + b];
                zg[g] = s;
            }
            float ig = 1.f/(1.f + __expf(-zg[0]));
            float fg = 1.f/(1.f + __expf(-zg[1]));
            float gg = tanhf(zg[2]);
            float og = 1.f/(1.f + __expf(-zg[3]));
            float c_old = __ldcg(&g_c[d][p][b*256 + hcol]);
            float h_old = hsS[b*HST + hcol + ((hcol >> 5) << 4)];
            float c_new = fg*c_old + ig*gg;
            float h_new = og*tanhf(c_new);
            float mv = maskS[b];
            float hv = mv*h_new + (1.f - mv)*h_old;
            float cv = mv*c_new + (1.f - mv)*c_old;
            g_h[d][p1][b*256 + hcol] = hv;
            g_c[d][p1][b*256 + hcol] = cv;
            out[((size_t)tx*BB + b)*512 + d*256 + hcol] = hv;
            out[(size_t)SQ*BB*512 + ((size_t)tx*BB + b)*512 + d*256 + hcol] = cv;
        }
        dir_barrier(bc, (++nbar) * NCTA_DIR);

        // ---- phase2a: stage h_new + prefetch XR ----
        {
            const float* hnp = g_h[d][p1];
            #pragma unroll
            for (int r = 0; r < 8; ++r) {
                int v = tid + r * NTHREADS;            // float4 id, 2048 total
                int b = v >> 6, kq = (v & 63) << 2;
                float4 vv = ldcg4(&hnp[b*256 + kq]);
                *(float4*)&hsS[b*HST + kq + ((kq >> 5) << 4)] = vv;
            }
            if (tid < 64) {
                int b = tid >> 1, half = tid & 1;
                const int ksg = rank >> 5, j0 = (rank & 31) * 8;
                float4 v = ldcg4(&g_XR[((((size_t)d*SQ + tx)*KSH + ksg)*BB + b)*256 + j0 + half*4]);
                zXR[(half*4+0)*33 + b] = v.x;
                zXR[(half*4+1)*33 + b] = v.y;
                zXR[(half*4+2)*33 + b] = v.z;
                zXR[(half*4+3)*33 + b] = v.w;
            }
        }
        __syncthreads();

        // ---- phase2b: r-GEMM 32x256 @ 256x8, f32x2, 8x2 micro, ksplit 16 ----
        {
            const int k2off = ks*16 + ((ks >> 1) << 4);
            const float* hp = hsS + bg*HST + k2off;
            const float* wp = WrS + cg*W2ST + k2off;
            unsigned long long acc[8][2];
            #pragma unroll
            for (int i = 0; i < 8; ++i) { acc[i][0] = 0ull; acc[i][1] = 0ull; }
            #pragma unroll
            for (int kk = 0; kk < 16; kk += 4) {
                ulonglong2 hr[8];
                #pragma unroll
                for (int i = 0; i < 8; ++i)
                    hr[i] = *(const ulonglong2*)(hp + i*4*HST + kk);
                #pragma unroll
                for (int j = 0; j < 2; ++j) {
                    ulonglong2 wv = *(const ulonglong2*)(wp + j*4*W2ST + kk);
                    #pragma unroll
                    for (int i = 0; i < 8; ++i) {
                        fma2(acc[i][j], hr[i].x, wv.x);
                        fma2(acc[i][j], hr[i].y, wv.y);
                    }
                }
            }
            const int store = !(ks & 1);
            const int kp = ks >> 1;
            #pragma unroll
            for (int i = 0; i < 8; ++i)
                #pragma unroll
                for (int j = 0; j < 2; ++j) {
                    float s = ull_sum(acc[i][j]);
                    s += __shfl_xor_sync(0xffffffffu, s, 16);
                    if (store) zp[(kp*8 + cg + 4*j)*33 + bg + 4*i] = s;
                }
        }
        __syncthreads();

        // ---- phase2c: reduce, r-gate, s update + output ----
        {
            int col = tid & 7, b = tid >> 3;
            const int ksg = rank >> 5;
            int j = (rank & 31)*8 + col;
            float s = zXR[col*33 + b];
            #pragma unroll
            for (int kp = 0; kp < 8; ++kp) s += zp[(kp*8 + col)*33 + b];
            float rg = 1.f/(1.f + __expf(-s));
            float s_old = __ldcg(&g_s[d][p][(ksg*BB + b)*256 + j]);
            float c_cur = __ldcg(&g_c[d][p1][b*256 + j]);
            float mv = maskS[b];
            float s_new = rg*s_old + (1.f - rg)*c_cur;
            float sv = mv*s_new + (1.f - mv)*s_old;
            g_s[d][p1][(ksg*BB + b)*256 + j] = sv;
            out[(size_t)2*SQ*BB*512 + (((size_t)ksg*SQ + tx)*BB + b)*512 + d*256 + j] = sv;
        }
        dir_barrier(bc, (++nbar) * NCTA_DIR);
    }
}

// SMEM floats: 32*772 + 16*772 + 8*388 + 8*16*33 + 16*33 + 8*33 + 32 = 45208
#define SMEM_BYTES (45208 * 4)

extern "C" void kernel_launch(void* const* d_in, const int* in_sizes, int n_in,
                              void* d_out, int out_size) {
    const float* x     = (const float*)d_in[0];
    const float* mask  = (const float*)d_in[1];
    const float* Wx    = (const float*)d_in[2];
    const float* Wh    = (const float*)d_in[3];
    const float* Ws    = (const float*)d_in[4];
    const float* bz    = (const float*)d_in[5];
    const float* Wrx   = (const float*)d_in[6];
    const float* Wrh   = (const float*)d_in[7];
    const float* br    = (const float*)d_in[8];
    const float* Wx_r  = (const float*)d_in[9];
    const float* Wh_r  = (const float*)d_in[10];
    const float* Ws_r  = (const float*)d_in[11];
    const float* b_r   = (const float*)d_in[12];
    const float* Wrx_r = (const float*)d_in[13];
    const float* Wrh_r = (const float*)d_in[14];
    const float* br_r  = (const float*)d_in[15];
    const int*   idxp  = (const int*)d_in[16];
    float* out = (float*)d_out;

    (void)cudaFuncSetAttribute(rnn_persist,
                               cudaFuncAttributeMaxDynamicSharedMemorySize, SMEM_BYTES);

    init_k<<<256, 256>>>();
    pre_gemm<<<dim3(24, 256, 2), 128>>>(x, Wx, Wrx, bz, br, Wx_r, Wrx_r, b_r, br_r);
    rnn_persist<<<128, NTHREADS, SMEM_BYTES>>>(mask, Wh, Ws, Wrh,
                                               Wh_r, Ws_r, Wrh_r, idxp, out);
}

// round 5
// speedup vs baseline: 2.0206x; 1.1177x over previous
#include <cuda_runtime.h>
#include <cstddef>

#define SQ   1024
#define BB   32
#define EE   256
#define HH   256
#define G4   1024
#define KSH  2
#define NCTA_DIR 64
#define NTH  256
#define HST  388     // 256 + 8*16 skew + 4
#define WST  388

typedef unsigned long long ull;

// ---------------- device scratch ----------------
__device__ float g_h[2][2][BB*HH];
__device__ float g_s[2][2][BB*HH];        // idx-slice only
__device__ unsigned int g_barcnt[2];
__device__ float g_XZ[(size_t)2*SQ*BB*G4];        // also reused as R scratch post-loop
__device__ float g_XR[(size_t)2*SQ*KSH*BB*HH];

__global__ void init_k() {
    int i = blockIdx.x * blockDim.x + threadIdx.x;
    if (i < 2*2*BB*HH) { ((float*)g_h)[i] = 0.f; ((float*)g_s)[i] = 0.f; }
    if (i < 2) g_barcnt[i] = 0u;
}

// ---------------- helpers ----------------
__device__ __forceinline__ void fma2(ull &d, ull a, ull b) {
    asm("fma.rn.f32x2 %0, %1, %2, %0;" : "+l"(d) : "l"(a), "l"(b));
}
__device__ __forceinline__ float ull_sum(ull v) {
    return __uint_as_float((unsigned)v) + __uint_as_float((unsigned)(v >> 32));
}
__device__ __forceinline__ void red_release(unsigned int* p) {
    asm volatile("red.release.gpu.global.add.u32 [%0], 1;" :: "l"(p) : "memory");
}
__device__ __forceinline__ unsigned int ld_acquire(const unsigned int* p) {
    unsigned int v;
    asm volatile("ld.acquire.gpu.global.u32 %0, [%1];" : "=r"(v) : "l"(p) : "memory");
    return v;
}
__device__ __forceinline__ float4 ldcg4(const float* p) {
    return __ldcg((const float4*)p);
}
__device__ __forceinline__ float sigmoidf_(float x) {
    return 1.f / (1.f + __expf(-x));
}

// ---------------- precompute GEMM (f32x2, 128x64 tile, 8x8 micro) ----------------
__global__ void __launch_bounds__(128) pre_gemm(
    const float* __restrict__ x,
    const float* __restrict__ Wx_f, const float* __restrict__ Wrx_f,
    const float* __restrict__ b_f,  const float* __restrict__ br_f,
    const float* __restrict__ Wx_r, const float* __restrict__ Wrx_r,
    const float* __restrict__ b_r,  const float* __restrict__ br_r)
{
    __shared__ float As[128*36];
    __shared__ float Bs[64*36];

    const int tid = threadIdx.x;
    const int d  = blockIdx.z;
    const int n0 = blockIdx.x * 64;
    const int m0 = blockIdx.y * 128;

    const float* Wx  = d ? Wx_r  : Wx_f;
    const float* Wrx = d ? Wrx_r : Wrx_f;
    const float* bz  = d ? b_r   : b_f;
    const float* brz = d ? br_r  : br_f;

    const int mg = tid & 15, ng = tid >> 4;

    ull acc[8][8];
    #pragma unroll
    for (int i = 0; i < 8; ++i)
        #pragma unroll
        for (int j = 0; j < 8; ++j) acc[i][j] = 0ull;

    for (int k0 = 0; k0 < 256; k0 += 32) {
        __syncthreads();
        #pragma unroll
        for (int r = 0; r < 8; ++r) {
            int v = tid + r * 128;
            int row = v >> 3, k4 = (v & 7) << 2;
            int m = m0 + row;
            float4 av = *(const float4*)&x[((size_t)(m & 31)*SQ + (m >> 5))*EE + k0 + k4];
            *(float4*)&As[row*36 + k4] = av;
        }
        #pragma unroll
        for (int r = 0; r < 4; ++r) {
            int v = tid + r * 128;
            int kk = v >> 4, n4 = (v & 15) << 2;
            int n = n0 + n4;
            float4 bv;
            if (n < 1024) {
                bv = *(const float4*)&Wx[(size_t)(k0 + kk)*G4 + n];
            } else {
                int rc = n - 1024, ks = rc >> 8, j = rc & 255;
                bv = *(const float4*)&Wrx[((size_t)ks*256 + (k0 + kk))*256 + j];
            }
            Bs[(n4+0)*36 + kk] = bv.x;
            Bs[(n4+1)*36 + kk] = bv.y;
            Bs[(n4+2)*36 + kk] = bv.z;
            Bs[(n4+3)*36 + kk] = bv.w;
        }
        __syncthreads();
        #pragma unroll
        for (int kk = 0; kk < 32; kk += 4) {
            ulonglong2 a[8];
            #pragma unroll
            for (int i = 0; i < 8; ++i)
                a[i] = *(const ulonglong2*)&As[(mg + 16*i)*36 + kk];
            #pragma unroll
            for (int j = 0; j < 8; ++j) {
                ulonglong2 bb = *(const ulonglong2*)&Bs[(ng + 8*j)*36 + kk];
                #pragma unroll
                for (int i = 0; i < 8; ++i) {
                    fma2(acc[i][j], a[i].x, bb.x);
                    fma2(acc[i][j], a[i].y, bb.y);
                }
            }
        }
    }
    #pragma unroll
    for (int i = 0; i < 8; ++i) {
        int m = m0 + mg + 16*i;
        int t = m >> 5, bbx = m & 31;
        #pragma unroll
        for (int j = 0; j < 8; ++j) {
            int n = n0 + ng + 8*j;
            float v = ull_sum(acc[i][j]);
            if (n < 1024) {
                v += bz[n];
                g_XZ[((size_t)d*32768 + m)*1024 + n] = v;
            } else {
                int rc = n - 1024, ks = rc >> 8, jj = rc & 255;
                v += brz[ks*256 + jj];
                g_XR[((((size_t)d*SQ + t)*KSH + ks)*BB + bbx)*256 + jj] = v;
            }
        }
    }
}

// ---------------- post: R = h @ Wrh[ko] + XR[ko]  (stored into g_XZ scratch) ----------------
__global__ void __launch_bounds__(128) post_rgemm(
    const float* __restrict__ outp,
    const float* __restrict__ Wrh_f, const float* __restrict__ Wrh_r,
    const int* __restrict__ idx_p)
{
    __shared__ float As[128*36];
    __shared__ float Bs[64*36];

    const int tid = threadIdx.x;
    const int d  = blockIdx.z;
    const int n0 = blockIdx.x * 64;
    const int m0 = blockIdx.y * 128;
    const int ko = 1 - *idx_p;
    const float* W = (d ? Wrh_r : Wrh_f) + (size_t)ko*256*256;

    const int mg = tid & 15, ng = tid >> 4;

    ull acc[8][8];
    #pragma unroll
    for (int i = 0; i < 8; ++i)
        #pragma unroll
        for (int j = 0; j < 8; ++j) acc[i][j] = 0ull;

    for (int k0 = 0; k0 < 256; k0 += 32) {
        __syncthreads();
        #pragma unroll
        for (int r = 0; r < 8; ++r) {
            int v = tid + r * 128;
            int row = v >> 3, k4 = (v & 7) << 2;
            int m = m0 + row;
            float4 av = *(const float4*)&outp[(size_t)m*512 + d*256 + k0 + k4];
            *(float4*)&As[row*36 + k4] = av;
        }
        #pragma unroll
        for (int r = 0; r < 4; ++r) {
            int v = tid + r * 128;
            int kk = v >> 4, n4 = (v & 15) << 2;
            float4 bv = *(const float4*)&W[(size_t)(k0 + kk)*256 + n0 + n4];
            Bs[(n4+0)*36 + kk] = bv.x;
            Bs[(n4+1)*36 + kk] = bv.y;
            Bs[(n4+2)*36 + kk] = bv.z;
            Bs[(n4+3)*36 + kk] = bv.w;
        }
        __syncthreads();
        #pragma unroll
        for (int kk = 0; kk < 32; kk += 4) {
            ulonglong2 a[8];
            #pragma unroll
            for (int i = 0; i < 8; ++i)
                a[i] = *(const ulonglong2*)&As[(mg + 16*i)*36 + kk];
            #pragma unroll
            for (int j = 0; j < 8; ++j) {
                ulonglong2 bb = *(const ulonglong2*)&Bs[(ng + 8*j)*36 + kk];
                #pragma unroll
                for (int i = 0; i < 8; ++i) {
                    fma2(acc[i][j], a[i].x, bb.x);
                    fma2(acc[i][j], a[i].y, bb.y);
                }
            }
        }
    }
    float* R = (float*)g_XZ;   // reuse as scratch (rnn finished)
    #pragma unroll
    for (int i = 0; i < 8; ++i) {
        int m = m0 + mg + 16*i;
        int t = m >> 5, bbx = m & 31;
        #pragma unroll
        for (int j = 0; j < 8; ++j) {
            int n = n0 + ng + 8*j;
            float v = ull_sum(acc[i][j])
                    + g_XR[((((size_t)d*SQ + t)*KSH + ko)*BB + bbx)*256 + n];
            R[((size_t)d*32768 + m)*256 + n] = v;
        }
    }
}

// ---------------- post: elementwise scan for s[k != idx] ----------------
__global__ void __launch_bounds__(256) post_scan(
    const float* __restrict__ mask,
    const int* __restrict__ idx_p,
    float* __restrict__ outp)
{
    int id = blockIdx.x * 256 + threadIdx.x;   // 2*32*256 = 16384
    int d = id >> 13, b = (id >> 8) & 31, j = id & 255;
    int ko = 1 - *idx_p;
    const float* R = (const float*)g_XZ + (size_t)d*32768*256;
    float s = 0.f;
    #pragma unroll 4
    for (int u = 0; u < SQ; ++u) {
        int t = d ? (SQ-1-u) : u;
        float rz = R[((size_t)t*BB + b)*256 + j];
        float r = sigmoidf_(rz);
        float c = outp[(size_t)SQ*BB*512 + ((size_t)t*BB + b)*512 + d*256 + j];
        float m = __ldg(&mask[b*SQ + t]);
        float sn = r*s + (1.f - r)*c;
        s = m*sn + (1.f - m)*s;
        outp[(size_t)2*SQ*BB*512 + (((size_t)ko*SQ + t)*BB + b)*512 + d*256 + j] = s;
    }
}

// ---------------- persistent recurrent kernel ----------------
__global__ void __launch_bounds__(NTH, 1) rnn_persist(
    const float* __restrict__ mask,
    const float* __restrict__ Wh_f, const float* __restrict__ Ws_f, const float* __restrict__ Wrh_f,
    const float* __restrict__ Wh_r, const float* __restrict__ Ws_r, const float* __restrict__ Wrh_r,
    const int*   __restrict__ idx_p,
    float* __restrict__ out)
{
    extern __shared__ float sm[];
    float* hS    = sm;                  // [32][388]
    float* sS    = hS + 32*HST;         // [32][388]
    float* WhS   = sS + 32*HST;         // [16][388]
    float* WsS   = WhS + 16*WST;        // [16][388]
    float* WrS   = WsS + 16*WST;        // [4][388]
    float* zp    = WrS + 4*WST;         // [8][16][33]
    float* zXZ   = zp + 8*16*33;        // [2][16][33] double-buffered
    float* zXR   = zXZ + 2*528;         // [4][33]
    float* maskS = zXR + 132;           // [32]

    const int tid  = threadIdx.x;
    const int d    = blockIdx.x >> 6;
    const int rank = blockIdx.x & 63;

    const float* Wh  = d ? Wh_r  : Wh_f;
    const float* Ws  = d ? Ws_r  : Ws_f;
    const float* Wrh = d ? Wrh_r : Wrh_f;
    const int sidx = *idx_p;

    // ---- weights into SMEM (once), k-skewed ----
    for (int i = tid; i < 16*256; i += NTH) {
        int lc = i >> 8, k = i & 255;
        int zcol = ((lc >> 2) << 8) + rank*4 + (lc & 3);
        int off = k + ((k >> 5) << 4);
        WhS[lc*WST + off] = Wh[(size_t)k*G4 + zcol];
        WsS[lc*WST + off] = Ws[(size_t)k*G4 + zcol];
    }
    for (int i = tid; i < 4*256; i += NTH) {
        int q = i >> 8, k = i & 255;
        WrS[q*WST + k + ((k >> 5) << 4)] = Wrh[((size_t)sidx*256 + k)*256 + rank*4 + q];
    }
    for (int i = tid; i < 32*HST; i += NTH) { hS[i] = 0.f; sS[i] = 0.f; }
    // prefetch XZ(u=0) into buffer 0
    if (tid < 128) {
        int b = tid >> 2, g = tid & 3;
        int tx0 = d ? SQ-1 : 0;
        float4 v = ldcg4(&g_XZ[(((size_t)d*SQ + tx0)*BB + b)*G4 + (g << 8) + rank*4]);
        zXZ[(g*4+0)*33 + b] = v.x;
        zXZ[(g*4+1)*33 + b] = v.y;
        zXZ[(g*4+2)*33 + b] = v.z;
        zXZ[(g*4+3)*33 + b] = v.w;
    }
    __syncthreads();

    unsigned int* bc = &g_barcnt[d];
    const int cg = tid & 3;
    const int bg = (tid >> 2) & 3;
    const int ks = tid >> 4;
    const int koff = ks*16 + ((ks >> 1) << 4);
    const int q = tid & 3, brow = tid >> 2;   // epilogue roles (tid<128)

    float hv = 0.f, cv = 0.f, sv = 0.f;       // register-resident state (tid<128)

    for (int u = 0; u < SQ; ++u) {
        const int p = u & 1, p1 = p ^ 1;
        const int tx = d ? (SQ-1-u) : u;

        // (1) prefetch mask + XR(u)
        if (tid < 32) {
            maskS[tid] = __ldg(&mask[tid*SQ + tx]);
        } else if (tid < 64) {
            int b = tid - 32;
            float4 v = ldcg4(&g_XR[((((size_t)d*SQ + tx)*KSH + sidx)*BB + b)*256 + rank*4]);
            zXR[0*33 + b] = v.x;
            zXR[1*33 + b] = v.y;
            zXR[2*33 + b] = v.z;
            zXR[3*33 + b] = v.w;
        }

        // (2) z_h: acc += h(u-1) @ Wh
        ull acc[8][4];
        #pragma unroll
        for (int i = 0; i < 8; ++i)
            #pragma unroll
            for (int j = 0; j < 4; ++j) acc[i][j] = 0ull;
        {
            const float* hp = hS + bg*HST + koff;
            const float* wp = WhS + cg*WST + koff;
            #pragma unroll
            for (int kk = 0; kk < 16; kk += 4) {
                ulonglong2 hr[8];
                #pragma unroll
                for (int i = 0; i < 8; ++i)
                    hr[i] = *(const ulonglong2*)(hp + i*4*HST + kk);
                #pragma unroll
                for (int j = 0; j < 4; ++j) {
                    ulonglong2 wv = *(const ulonglong2*)(wp + j*4*WST + kk);
                    #pragma unroll
                    for (int i = 0; i < 8; ++i) {
                        fma2(acc[i][j], hr[i].x, wv.x);
                        fma2(acc[i][j], hr[i].y, wv.y);
                    }
                }
            }
        }

        // (3) wait for s(u-1), stage it (hidden behind z_h above)
        if (u > 0) {
            if (tid == 0) { while (ld_acquire(bc) < (unsigned)(2u*u)*NCTA_DIR) {} }
            __syncthreads();
            const float* ssrc = g_s[d][p];
            #pragma unroll
            for (int r = 0; r < 8; ++r) {
                int v = tid + r * NTH;
                int b = v >> 6, kq = (v & 63) << 2;
                float4 vv = ldcg4(&ssrc[b*256 + kq]);
                *(float4*)&sS[b*HST + kq + ((kq >> 5) << 4)] = vv;
            }
            __syncthreads();
        }

        // (4) z_s: acc += s(u-1) @ Ws
        {
            const float* sp = sS + bg*HST + koff;
            const float* wp = WsS + cg*WST + koff;
            #pragma unroll
            for (int kk = 0; kk < 16; kk += 4) {
                ulonglong2 hr[8];
                #pragma unroll
                for (int i = 0; i < 8; ++i)
                    hr[i] = *(const ulonglong2*)(sp + i*4*HST + kk);
                #pragma unroll
                for (int j = 0; j < 4; ++j) {
                    ulonglong2 wv = *(const ulonglong2*)(wp + j*4*WST + kk);
                    #pragma unroll
                    for (int i = 0; i < 8; ++i) {
                        fma2(acc[i][j], hr[i].x, wv.x);
                        fma2(acc[i][j], hr[i].y, wv.y);
                    }
                }
            }
        }

        // (5) partial reduce + store
        {
            const int store = !(ks & 1);
            const int kp = ks >> 1;
            #pragma unroll
            for (int i = 0; i < 8; ++i)
                #pragma unroll
                for (int j = 0; j < 4; ++j) {
                    float s = ull_sum(acc[i][j]);
                    s += __shfl_xor_sync(0xffffffffu, s, 16);
                    if (store) zp[(kp*16 + cg + 4*j)*33 + bg + 4*i] = s;
                }
        }
        __syncthreads();

        // p1c: gates + h/c update + publish (tid<128)
        if (tid < 128) {
            const float* zb = zXZ + (u & 1) * 528;
            float zg[4];
            #pragma unroll
            for (int g = 0; g < 4; ++g) {
                int lc = g*4 + q;
                float s = zb[lc*33 + brow];
                #pragma unroll
                for (int kp = 0; kp < 8; ++kp) s += zp[(kp*16 + lc)*33 + brow];
                zg[g] = s;
            }
            float ig = sigmoidf_(zg[0]);
            float fg = sigmoidf_(zg[1]);
            float gg = tanhf(zg[2]);
            float og = sigmoidf_(zg[3]);
            float c_new = fg*cv + ig*gg;
            float h_new = og*tanhf(c_new);
            float mv = maskS[brow];
            hv = mv*h_new + (1.f - mv)*hv;
            cv = mv*c_new + (1.f - mv)*cv;
            int hcol = rank*4 + q;
            g_h[d][p1][brow*256 + hcol] = hv;
            out[((size_t)tx*BB + brow)*512 + d*256 + hcol] = hv;
            out[(size_t)SQ*BB*512 + ((size_t)tx*BB + brow)*512 + d*256 + hcol] = cv;
        }

        // (6) arrive(h); overlap: tid>=128 prefetch XZ(u+1); tid0 spins wait(h)
        __syncthreads();
        if (tid == 0) red_release(bc);
        if (tid >= 128 && u + 1 < SQ) {
            int t2 = tid - 128;
            int b = t2 >> 2, g = t2 & 3;
            int tx2 = d ? (SQ-2-u) : (u+1);
            float4 v = ldcg4(&g_XZ[(((size_t)d*SQ + tx2)*BB + b)*G4 + (g << 8) + rank*4]);
            float* zb2 = zXZ + ((u+1) & 1) * 528;
            zb2[(g*4+0)*33 + b] = v.x;
            zb2[(g*4+1)*33 + b] = v.y;
            zb2[(g*4+2)*33 + b] = v.z;
            zb2[(g*4+3)*33 + b] = v.w;
        }
        if (tid == 0) { while (ld_acquire(bc) < (unsigned)(2u*u + 1)*NCTA_DIR) {} }
        __syncthreads();

        // (7) stage h(u) (kept resident for next step's z_h too)
        {
            const float* hsrc = g_h[d][p1];
            #pragma unroll
            for (int r = 0; r < 8; ++r) {
                int v = tid + r * NTH;
                int b = v >> 6, kq = (v & 63) << 2;
                float4 vv = ldcg4(&hsrc[b*256 + kq]);
                *(float4*)&hS[b*HST + kq + ((kq >> 5) << 4)] = vv;
            }
        }
        __syncthreads();

        // (8) r-GEMM (idx slice, 4 cols): a2 = h(u) @ Wrh[idx]
        {
            ull a2[8];
            #pragma unroll
            for (int i = 0; i < 8; ++i) a2[i] = 0ull;
            const float* hp = hS + bg*HST + koff;
            const float* wr = WrS + cg*WST + koff;
            #pragma unroll
            for (int kk = 0; kk < 16; kk += 4) {
                ulonglong2 wv = *(const ulonglong2*)(wr + kk);
                #pragma unroll
                for (int i = 0; i < 8; ++i) {
                    ulonglong2 hr = *(const ulonglong2*)(hp + i*4*HST + kk);
                    fma2(a2[i], hr.x, wv.x);
                    fma2(a2[i], hr.y, wv.y);
                }
            }
            const int store = !(ks & 1);
            const int kp = ks >> 1;
            #pragma unroll
            for (int i = 0; i < 8; ++i) {
                float s = ull_sum(a2[i]);
                s += __shfl_xor_sync(0xffffffffu, s, 16);
                if (store) zp[(kp*4 + cg)*33 + bg + 4*i] = s;
            }
        }
        __syncthreads();

        // (9) p2c: r-gate + s update + publish (tid<128)
        if (tid < 128) {
            float rz = zXR[q*33 + brow];
            #pragma unroll
            for (int kp = 0; kp < 8; ++kp) rz += zp[(kp*4 + q)*33 + brow];
            float rg = sigmoidf_(rz);
            float mv = maskS[brow];
            float s_new = rg*sv + (1.f - rg)*cv;
            sv = mv*s_new + (1.f - mv)*sv;
            int col = rank*4 + q;
            g_s[d][p1][brow*256 + col] = sv;
            out[(size_t)2*SQ*BB*512 + (((size_t)sidx*SQ + tx)*BB + brow)*512 + d*256 + col] = sv;
        }

        // (10) arrive(s)
        __syncthreads();
        if (tid == 0) red_release(bc);
    }
}

// SMEM floats: 2*32*388 + 2*16*388 + 4*388 + 4224 + 1056 + 132 + 32 = 44244
#define SMEM_BYTES (44244 * 4)

extern "C" void kernel_launch(void* const* d_in, const int* in_sizes, int n_in,
                              void* d_out, int out_size) {
    const float* x     = (const float*)d_in[0];
    const float* mask  = (const float*)d_in[1];
    const float* Wx    = (const float*)d_in[2];
    const float* Wh    = (const float*)d_in[3];
    const float* Ws    = (const float*)d_in[4];
    const float* bz    = (const float*)d_in[5];
    const float* Wrx   = (const float*)d_in[6];
    const float* Wrh   = (const float*)d_in[7];
    const float* br    = (const float*)d_in[8];
    const float* Wx_r  = (const float*)d_in[9];
    const float* Wh_r  = (const float*)d_in[10];
    const float* Ws_r  = (const float*)d_in[11];
    const float* b_r   = (const float*)d_in[12];
    const float* Wrx_r = (const float*)d_in[13];
    const float* Wrh_r = (const float*)d_in[14];
    const float* br_r  = (const float*)d_in[15];
    const int*   idxp  = (const int*)d_in[16];
    float* out = (float*)d_out;

    (void)cudaFuncSetAttribute(rnn_persist,
                               cudaFuncAttributeMaxDynamicSharedMemorySize, SMEM_BYTES);

    init_k<<<256, 256>>>();
    pre_gemm<<<dim3(24, 256, 2), 128>>>(x, Wx, Wrx, bz, br, Wx_r, Wrx_r, b_r, br_r);
    rnn_persist<<<128, NTH, SMEM_BYTES>>>(mask, Wh, Ws, Wrh,
                                          Wh_r, Ws_r, Wrh_r, idxp, out);
    post_rgemm<<<dim3(4, 256, 2), 128>>>(out, Wrh, Wrh_r, idxp);
    post_scan<<<64, 256>>>(mask, idxp, out);
}